// round 15
// baseline (speedup 1.0000x reference)
#include <cuda_runtime.h>
#include <cstdint>
#include <cstddef>

#define NS 512
#define NB 1024
#define NT 64

__device__ float g_partial[NB];
__device__ unsigned int g_ctr = 0;

typedef unsigned long long u64;

__device__ __forceinline__ u64 pack2(float lo, float hi) {
    u64 r; asm("mov.b64 %0, {%1, %2};" : "=l"(r) : "f"(lo), "f"(hi)); return r;
}
__device__ __forceinline__ void unpack2(u64 v, float& lo, float& hi) {
    asm("mov.b64 {%0, %1}, %2;" : "=f"(lo), "=f"(hi) : "l"(v));
}
__device__ __forceinline__ void fma2(u64& acc, u64 a, u64 b) {
    asm("fma.rn.f32x2 %0, %1, %2, %0;" : "+l"(acc) : "l"(a), "l"(b));
}
__device__ __forceinline__ u64 add2(u64 a, u64 b) {
    u64 r; asm("add.rn.f32x2 %0, %1, %2;" : "=l"(r) : "l"(a), "l"(b)); return r;
}
__device__ __forceinline__ u64 mul2(u64 a, u64 b) {
    u64 r; asm("mul.rn.f32x2 %0, %1, %2;" : "=l"(r) : "l"(a), "l"(b)); return r;
}
__device__ __forceinline__ float frcp(float x) {
    float r; asm("rcp.approx.f32 %0, %1;" : "=f"(r) : "f"(x)); return r;
}
// exp(x) * 2^-6 as one FFMA + one MUFU.EX2
__device__ __forceinline__ float expm6(float x) {
    return exp2f(fmaf(x, 1.4426950408889634f, -6.0f));
}
__device__ __forceinline__ void sts64(u64* p, u64 v) {
    asm volatile("st.shared.b64 [%0], %1;" :: "l"(p), "l"(v) : "memory");
}
__device__ __forceinline__ void cp_async8(void* smem_dst, const void* gsrc) {
    unsigned s = (unsigned)__cvta_generic_to_shared(smem_dst);
    asm volatile("cp.async.ca.shared.global [%0], [%1], 8;" :: "r"(s), "l"(gsrc));
}
#define CP_COMMIT() asm volatile("cp.async.commit_group;" ::: "memory")
#define CP_WAIT(n)  asm volatile("cp.async.wait_group %0;" :: "n"(n) : "memory")

__global__ void __launch_bounds__(32)
crf_kernel(const float* __restrict__ em,
           const float* __restrict__ trans,
           const float* __restrict__ start_t,
           const float* __restrict__ end_t,
           const int* __restrict__ tags,
           const int* __restrict__ mask,
           float* __restrict__ out) {
    __shared__ __align__(16) u64   qsmA[2][32], qsmB[2][32];
    __shared__ __align__(16) float emringA[8][NT], emringB[8][NT];

    const int lane = threadIdx.x;        // one warp = TWO chains
    const int bA   = blockIdx.x * 2;
    const int bB   = bA + 1;
    const int c0   = 2 * lane;           // my two columns for both chains
    const size_t SSTR = (size_t)NB * NT;

    // ---------------- numerators: gold-path scores ----------------
    float scA = 0.f, scB = 0.f;
    int msumA = 0, msumB = 0;
#define GOLD(X)                                                                    \
    {                                                                              \
        float sc = 0.f; int msum = 0;                                              \
        _Pragma("unroll")                                                          \
        for (int k = 0; k < 16; k++) {                                             \
            int s = 1 + lane + (k << 5);                                           \
            if (s < NS) {                                                          \
                int tp = tags[(s - 1) * NB + b##X];                                \
                int tc = tags[s * NB + b##X];                                      \
                int mv = mask[s * NB + b##X];                                      \
                float term = trans[tp * NT + tc] + em[((size_t)s * NB + b##X) * NT + tc]; \
                sc += term * (float)mv;                                            \
                msum += mv;                                                        \
            }                                                                      \
        }                                                                          \
        _Pragma("unroll")                                                          \
        for (int off = 16; off; off >>= 1) {                                       \
            sc   += __shfl_xor_sync(0xffffffffu, sc, off);                         \
            msum += __shfl_xor_sync(0xffffffffu, msum, off);                       \
        }                                                                          \
        int t0 = tags[b##X];                                                       \
        sc += start_t[t0] + em[(size_t)b##X * NT + t0];                            \
        int seq_end = mask[b##X] + msum - 1;                                       \
        int lt = tags[(size_t)seq_end * NB + b##X];                                \
        sc += end_t[lt];                                                           \
        sc##X = sc; msum##X = msum;                                                \
    }
    GOLD(A)
    GOLD(B)
#undef GOLD

    // ---------------- mask bitsets ----------------
    unsigned mbitsA = 0, mbitsB = 0;
#pragma unroll
    for (int k = 0; k < 16; k++) {
        int s = 16 * lane + k;
        mbitsA |= (unsigned)(mask[s * NB + bA] & 1) << k;
        mbitsB |= (unsigned)(mask[s * NB + bB] & 1) << k;
    }

    // ---------------- cp.async em pipelines: slots for steps 1..8 (paired groups) ----
    const float* embA = em + (size_t)bA * NT + c0;
    const float* embB = em + (size_t)bB * NT + c0;
#pragma unroll
    for (int t = 1; t <= 8; t++) {
        cp_async8(&emringA[t & 7][c0], embA + (size_t)t * SSTR);
        cp_async8(&emringB[t & 7][c0], embB + (size_t)t * SSTR);
        CP_COMMIT();
    }

    // ---------------- E row-pair packed (shared by both chains) ----------------
    u64 EC0[32], EC1[32];
#pragma unroll
    for (int i = 0; i < 32; i++) {
        float2 ta = *reinterpret_cast<const float2*>(trans + (2 * i) * NT + c0);
        float2 tb = *reinterpret_cast<const float2*>(trans + (2 * i + 1) * NT + c0);
        EC0[i] = pack2(__expf(ta.x), __expf(tb.x));
        EC1[i] = pack2(__expf(ta.y), __expf(tb.y));
    }

    // ---------------- init recursion state ----------------
    u64 yA, yB;
    {
        float2 e0 = *reinterpret_cast<const float2*>(embA);
        float2 s2 = *reinterpret_cast<const float2*>(start_t + c0);
        yA = pack2(__expf(s2.x + e0.x), __expf(s2.y + e0.y));
        sts64(&qsmA[1][lane], yA);
        float2 e0b = *reinterpret_cast<const float2*>(embB);
        yB = pack2(__expf(s2.x + e0b.x), __expf(s2.y + e0b.y));
        sts64(&qsmB[1][lane], yB);
    }
    float MtotA = 0.f, MtotB = 0.f;

    u64 eemA, eemB;
    {
        CP_WAIT(7);
        float2 e1a = *reinterpret_cast<const float2*>(&emringA[1][c0]);
        eemA = pack2(expm6(e1a.x), expm6(e1a.y));
        float2 e1b = *reinterpret_cast<const float2*>(&emringB[1][c0]);
        eemB = pack2(expm6(e1b.x), expm6(e1b.y));
    }
    __syncwarp();

// One step-index for BOTH chains, interleaved in one straight-line block.
#define CRF_STEP(S, P, RN)                                                         \
    {                                                                              \
        const ulonglong2* qa = reinterpret_cast<const ulonglong2*>(qsmA[P]);       \
        const ulonglong2* qb = reinterpret_cast<const ulonglong2*>(qsmB[P]);       \
        u64 a0 = 0, a1 = 0, a2 = 0, a3 = 0, a4 = 0, a5 = 0, a6 = 0, a7 = 0;        \
        u64 g0 = 0, g1 = 0, g2 = 0, g3 = 0, g4 = 0, g5 = 0, g6 = 0, g7 = 0;        \
        _Pragma("unroll")                                                          \
        for (int m = 0; m < 8; m++) {                                              \
            ulonglong2 qa0 = qa[2 * m];                                            \
            ulonglong2 qa1 = qa[2 * m + 1];                                        \
            ulonglong2 qb0 = qb[2 * m];                                            \
            ulonglong2 qb1 = qb[2 * m + 1];                                        \
            fma2(a0, qa0.x, EC0[4 * m]);     fma2(a1, qa0.x, EC1[4 * m]);          \
            fma2(g0, qb0.x, EC0[4 * m]);     fma2(g1, qb0.x, EC1[4 * m]);          \
            fma2(a2, qa0.y, EC0[4 * m + 1]); fma2(a3, qa0.y, EC1[4 * m + 1]);      \
            fma2(g2, qb0.y, EC0[4 * m + 1]); fma2(g3, qb0.y, EC1[4 * m + 1]);      \
            fma2(a4, qa1.x, EC0[4 * m + 2]); fma2(a5, qa1.x, EC1[4 * m + 2]);      \
            fma2(g4, qb1.x, EC0[4 * m + 2]); fma2(g5, qb1.x, EC1[4 * m + 2]);      \
            fma2(a6, qa1.y, EC0[4 * m + 3]); fma2(a7, qa1.y, EC1[4 * m + 3]);      \
            fma2(g6, qb1.y, EC0[4 * m + 3]); fma2(g7, qb1.y, EC1[4 * m + 3]);      \
        }                                                                          \
        u64 A0 = add2(add2(a0, a2), add2(a4, a6));                                 \
        u64 A1 = add2(add2(a1, a3), add2(a5, a7));                                 \
        u64 G0 = add2(add2(g0, g2), add2(g4, g6));                                 \
        u64 G1 = add2(add2(g1, g3), add2(g5, g7));                                 \
        float alo0, ahi0, alo1, ahi1, glo0, ghi0, glo1, ghi1;                      \
        unpack2(A0, alo0, ahi0); unpack2(A1, alo1, ahi1);                          \
        unpack2(G0, glo0, ghi0); unpack2(G1, glo1, ghi1);                          \
        int mkA = (int)((mwordA >> ((S) & 15)) & 1u);                              \
        int mkB = (int)((mwordB >> ((S) & 15)) & 1u);                              \
        u64 cA = mul2(pack2(alo0 + ahi0, alo1 + ahi1), eemA);                      \
        u64 cB = mul2(pack2(glo0 + ghi0, glo1 + ghi1), eemB);                      \
        if (mkA) yA = cA;                                                          \
        if (mkB) yB = cB;                                                          \
        if (RN) {                                                                  \
            float fa, fx; unpack2(yA, fa, fx);                                     \
            float fb;     unpack2(yB, fb, fx);                                     \
            float fA = __shfl_sync(0xffffffffu, fa, 0);                            \
            float fB = __shfl_sync(0xffffffffu, fb, 0);                            \
            float ra = frcp(fA), rb = frcp(fB);                                    \
            yA = mul2(yA, pack2(ra, ra));                                          \
            yB = mul2(yB, pack2(rb, rb));                                          \
            MtotA += __logf(fA);                                                   \
            MtotB += __logf(fB);                                                   \
        }                                                                          \
        sts64(&qsmA[(P) ^ 1][lane], yA);                                           \
        sts64(&qsmB[(P) ^ 1][lane], yB);                                           \
        __syncwarp();                                                              \
        CP_WAIT(6);                                                                \
        float2 ena = *reinterpret_cast<const float2*>(&emringA[((S) + 1) & 7][c0]); \
        float2 enb = *reinterpret_cast<const float2*>(&emringB[((S) + 1) & 7][c0]); \
        eemA = pack2(expm6(ena.x), expm6(ena.y));                                  \
        eemB = pack2(expm6(enb.x), expm6(enb.y));                                  \
        int t = ((S) + 8 < NS) ? ((S) + 8) : (NS - 1);                             \
        cp_async8(&emringA[((S) + 8) & 7][c0], embA + (size_t)t * SSTR);           \
        cp_async8(&emringB[((S) + 8) & 7][c0], embB + (size_t)t * SSTR);           \
        CP_COMMIT();                                                               \
    }

    // prologue: steps 1..7, renorm at step 7
    unsigned mwordA = __shfl_sync(0xffffffffu, mbitsA, 0);
    unsigned mwordB = __shfl_sync(0xffffffffu, mbitsB, 0);
    CRF_STEP(1, 1, false)
    CRF_STEP(2, 0, false)
    CRF_STEP(3, 1, false)
    CRF_STEP(4, 0, false)
    CRF_STEP(5, 1, false)
    CRF_STEP(6, 0, false)
    CRF_STEP(7, 1, true)

    // main: 63 blocks of 8 steps, renorm fused into last step of each block
    for (int o = 1; o < 64; o++) {
        const int s0 = o << 3;
        mwordA = __shfl_sync(0xffffffffu, mbitsA, o >> 1);
        mwordB = __shfl_sync(0xffffffffu, mbitsB, o >> 1);
        CRF_STEP(s0,     0, false)
        CRF_STEP(s0 + 1, 1, false)
        CRF_STEP(s0 + 2, 0, false)
        CRF_STEP(s0 + 3, 1, false)
        CRF_STEP(s0 + 4, 0, false)
        CRF_STEP(s0 + 5, 1, false)
        CRF_STEP(s0 + 6, 0, false)
        CRF_STEP(s0 + 7, 1, true)
    }
#undef CRF_STEP

    // ---------------- normalizers ----------------
#define FIN(X)                                                                     \
    {                                                                              \
        float2 e2 = *reinterpret_cast<const float2*>(end_t + c0);                  \
        float y0, y1; unpack2(y##X, y0, y1);                                       \
        float v = y0 * __expf(e2.x) + y1 * __expf(e2.y);                           \
        _Pragma("unroll")                                                          \
        for (int off = 16; off; off >>= 1)                                         \
            v += __shfl_xor_sync(0xffffffffu, v, off);                             \
        if (lane == 0) {                                                           \
            const float LOG64 = 4.1588830833596715f;                               \
            g_partial[b##X] = sc##X - (Mtot##X + (float)msum##X * LOG64 + __logf(v)); \
        }                                                                          \
    }
    FIN(A)
    FIN(B)
#undef FIN

    if (lane == 0) __threadfence();
    __syncwarp();

    // ---------------- merged deterministic final reduction (last block) ----------------
    int last = 0;
    if (lane == 0) {
        unsigned int old = atomicAdd(&g_ctr, 1);
        last = (old == (unsigned int)(gridDim.x - 1));
    }
    last = __shfl_sync(0xffffffffu, last, 0);
    if (last) {
        __threadfence();
        float s = 0.f;
#pragma unroll
        for (int i = 0; i < NB / 32; i++)
            s += g_partial[lane + i * 32];
#pragma unroll
        for (int off = 16; off; off >>= 1)
            s += __shfl_xor_sync(0xffffffffu, s, off);
        if (lane == 0) { out[0] = s; g_ctr = 0; }
    }
}

extern "C" void kernel_launch(void* const* d_in, const int* in_sizes, int n_in,
                              void* d_out, int out_size) {
    const float* em    = (const float*)d_in[0];
    const float* trans = (const float*)d_in[1];
    const float* st    = (const float*)d_in[2];
    const float* et    = (const float*)d_in[3];
    const int*   tags  = (const int*)d_in[4];
    const int*   mask  = (const int*)d_in[5];

    crf_kernel<<<NB / 2, 32>>>(em, trans, st, et, tags, mask, (float*)d_out);
}